// round 7
// baseline (speedup 1.0000x reference)
#include <cuda_runtime.h>
#include <math.h>

// Problem constants
#define NBc   16
#define NAc   5
#define NKc   9
#define NCc   13
#define NHc   38
#define NWc   38
#define MAXTc 50
#define NPIX  (NHc*NWc)        // 1444
#define NANCH (NAc*NPIX)       // 7220
#define NTOTc (NBc*NANCH)      // 115520
#define CHPA  (2*NKc+1+NCc)    // 32
#define TROW  21

#define TPB   256
#define CPB   64                           // cells per block (4 threads/cell)
#define BPB   ((NANCH + CPB - 1)/CPB)      // 113 blocks per batch
#define NBLK  (NBc*BPB)                    // 1808 blocks

// meta record in shared: [0]=key bits, [1]=tconf, [2]=cls, [3]=pad,
//                        [4..21]=(gx,gy)*9 px, [22..39]=(vx,vy)*9
#define MSTRIDE 40

#define SCX   (640.0f/38.0f)
#define SCY   (480.0f/38.0f)
#define DENOM9   57.50150489f
#define STHRESH  34.50090293f   // 0.6 * 9 * (e^2 - 1)

__device__ float g_part[NBLK][2];
__device__ int   g_cnt = 0;

__device__ __forceinline__ float sigf(float x) { return 1.0f / (1.0f + __expf(-x)); }

__global__ void __launch_bounds__(TPB)
k_main(const float* __restrict__ out,
       const float* __restrict__ tgt,
       const float* __restrict__ anc,
       const void*  __restrict__ epoch_ptr,
       float* __restrict__ d_out) {
    __shared__ __align__(16) float s_meta[MAXTc*MSTRIDE];
    __shared__ float  s_t[MAXTc*TROW];
    __shared__ int    s_nv;
    __shared__ float2 s_wred[TPB/32];
    __shared__ bool   s_last;

    const int tid   = threadIdx.x;
    const int lane  = tid & 31;
    const int wid   = tid >> 5;
    const int b     = blockIdx.x / BPB;
    const int split = tid & 3;                       // corner-split lane (0..3)
    const unsigned gmask = 0xFu << (lane & ~3);      // this cell-group's lanes
    const int cell  = (blockIdx.x % BPB) * CPB + (tid >> 2);
    const bool ok   = (cell < NANCH);

    // ---- per-cell loads split by corner: lane owns k = split + 4j (j=0..2) --
    int a = 0, h = 0, w = 0;
    const float* baseo = out;
    float Px0=0, Py0=0, Px1=0, Py1=0, Px2=0, Py2=0;
    float confv_here = 0.0f;
    const int k0 = split, k1 = split + 4, k2 = split + 8;  // k2 valid only split==0
    if (ok) {
        a = cell / NPIX;
        int pix = cell % NPIX;
        h = pix / NWc; w = pix % NWc;
        baseo = out + ((size_t)(b * NAc + a) * CHPA) * NPIX + pix;
        {
            float xv = baseo[(2*k0)   * NPIX];
            float yv = baseo[(2*k0+1) * NPIX];
            if (k0 == 0) { xv = sigf(xv); yv = sigf(yv); }
            Px0 = (xv + (float)w) * SCX;  Py0 = (yv + (float)h) * SCY;
        }
        {
            float xv = baseo[(2*k1)   * NPIX];
            float yv = baseo[(2*k1+1) * NPIX];
            Px1 = (xv + (float)w) * SCX;  Py1 = (yv + (float)h) * SCY;
        }
        if (k2 < NKc) {
            float xv = baseo[(2*k2)   * NPIX];
            float yv = baseo[(2*k2+1) * NPIX];
            Px2 = (xv + (float)w) * SCX;  Py2 = (yv + (float)h) * SCY;
        }
        if (split == 1) confv_here = sigf(baseo[(2*NKc) * NPIX]);
    }
    // broadcast conf within the 4-lane cell group (all 4 lanes execute)
    const float confv = __shfl_sync(gmask, confv_here, 1, 4);

    // ---- targets -> shared (coalesced) --------------------------------------
    for (int i = tid; i < MAXTc*TROW; i += TPB)
        s_t[i] = tgt[(size_t)b * (MAXTc*TROW) + i];
    __syncthreads();

    // ---- validity prefix via ballots (warp 0) -------------------------------
    if (wid == 0) {
        unsigned m0 = __ballot_sync(0xFFFFFFFFu, s_t[lane*TROW + 1] != 0.0f);
        unsigned m1 = __ballot_sync(0xFFFFFFFFu,
                          (lane < MAXTc - 32) && (s_t[(lane+32)*TROW + 1] != 0.0f));
        if (lane == 0) {
            int nv;
            if (~m0) nv = __ffs(~m0) - 1;
            else {
                unsigned inv = (~m1) & ((1u << (MAXTc - 32)) - 1u);
                nv = inv ? 32 + __ffs(inv) - 1 : MAXTc;
            }
            s_nv = nv;
        }
    }
    __syncthreads();
    const int nv = s_nv;

    // ---- per-target meta straight into shared -------------------------------
    if (tid < nv) {
        const int t = tid;
        const float* tb = &s_t[t*TROW];
        float* mr = &s_meta[t*MSTRIDE];

        float gw = tb[19] * (float)NWc;
        float gh = tb[20] * (float)NHc;
        float best = -1.0f; int bn = 0;
        #pragma unroll
        for (int aa = 0; aa < NAc; ++aa) {
            float aw = anc[2*aa], ah = anc[2*aa+1];
            float cw = fminf(gw, aw), ch = fminf(gh, ah);
            float iou = 0.0f;
            if (cw > 0.0f && ch > 0.0f) {
                float ca = cw * ch;
                iou = ca / (gw * gh + aw * ah - ca);
            }
            if (iou > best) { best = iou; bn = aa; }
        }
        int gi0 = (int)floorf(tb[1] * (float)NWc);
        int gj0 = (int)floorf(tb[2] * (float)NHc);
        mr[0] = __int_as_float((bn << 12) | (gj0 << 6) | gi0);
        mr[2] = tb[0];
        mr[3] = 0.0f;

        float gxp[NKc], gyp[NKc];
        #pragma unroll
        for (int k = 0; k < NKc; ++k) {
            float gx = tb[1 + 2*k], gy = tb[2 + 2*k];
            gxp[k] = gx * 640.0f;  gyp[k] = gy * 480.0f;
            mr[4  + 2*k] = gxp[k];
            mr[5  + 2*k] = gyp[k];
            mr[22 + 2*k] = gx * (float)NWc - (float)gi0;
            mr[23 + 2*k] = gy * (float)NHc - (float)gj0;
        }

        // tconf at pidx-shifted cell
        long long p = (long long)b * NANCH - NPIX + (long long)gj0 * NWc + gi0;
        const long long tot = NTOTc;
        p = ((p % tot) + tot) % tot;
        int b2  = (int)(p / NANCH);
        int rem = (int)(p % NANCH);
        int a2  = rem / NPIX;
        int px2 = rem % NPIX;
        int h2 = px2 / NWc, w2 = px2 % NWc;
        const float* bo2 = out + ((size_t)(b2 * NAc + a2) * CHPA) * NPIX + px2;

        float s = 0.0f;
        #pragma unroll
        for (int k = 0; k < NKc; ++k) {
            float xv = bo2[(2*k)   * NPIX];
            float yv = bo2[(2*k+1) * NPIX];
            if (k == 0) { xv = sigf(xv); yv = sigf(yv); }
            float qx = (xv + (float)w2) * SCX;
            float qy = (yv + (float)h2) * SCY;
            float dx = gxp[k] - qx;
            float dy = gyp[k] - qy;
            float d2 = fmaf(dx, dx, dy * dy);
            if (d2 < 6400.0f) s += __expf(2.0f - sqrtf(d2) * 0.025f) - 1.0f;
        }
        mr[1] = s * (1.0f / DENOM9);
    }
    __syncthreads();

    // ---- match scan (targets split across the 4 lanes; uniform control) -----
    int m = -1;
    if (ok) {
        const int mykey = (a << 12) | (h << 6) | w;
        for (int t = split; t < nv; t += 4)
            if (__float_as_int(s_meta[t*MSTRIDE]) == mykey) m = t;
    }
    // executed by ALL lanes -> full mask legal
    m = max(m, __shfl_xor_sync(0xFFFFFFFFu, m, 1));
    m = max(m, __shfl_xor_sync(0xFFFFFFFFu, m, 2));

    // ---- silence scan: cooperative over 4 lanes (group-mask shuffles) -------
    int silent = 0;
    if (m < 0) {           // group-uniform; may diverge across groups (gmask ok)
        for (int t = 0; t < nv; ++t) {
            float ssum = 0.0f;
            if (ok) {
                const float* gp = s_meta + t*MSTRIDE + 4;
                {
                    float dx = Px0 - gp[2*k0], dy = Py0 - gp[2*k0+1];
                    float d2 = fmaf(dx, dx, dy * dy);
                    if (d2 < 6400.0f) ssum += __expf(2.0f - sqrtf(d2) * 0.025f) - 1.0f;
                }
                {
                    float dx = Px1 - gp[2*k1], dy = Py1 - gp[2*k1+1];
                    float d2 = fmaf(dx, dx, dy * dy);
                    if (d2 < 6400.0f) ssum += __expf(2.0f - sqrtf(d2) * 0.025f) - 1.0f;
                }
                if (k2 < NKc) {
                    float dx = Px2 - gp[2*k2], dy = Py2 - gp[2*k2+1];
                    float d2 = fmaf(dx, dx, dy * dy);
                    if (d2 < 6400.0f) ssum += __expf(2.0f - sqrtf(d2) * 0.025f) - 1.0f;
                }
            }
            // 4-lane butterfly with GROUP mask (legal under group divergence)
            ssum += __shfl_xor_sync(gmask, ssum, 1, 4);
            ssum += __shfl_xor_sync(gmask, ssum, 2, 4);
            if (ssum > STHRESH) { silent = 1; break; }   // group-uniform break
        }
    }

    // ---- loss terms (split 0 of each cell only) ----------------------------
    float baseLoss = 0.0f, confLoss = 0.0f;
    if (ok && split == 0) {
        if (m >= 0) {
            const float* mr = &s_meta[m*MSTRIDE];
            #pragma unroll
            for (int k = 0; k < NKc; ++k) {
                float xv = baseo[(2*k)   * NPIX];
                float yv = baseo[(2*k+1) * NPIX];
                if (k == 0) { xv = sigf(xv); yv = sigf(yv); }
                float dx = xv - mr[22 + 2*k];
                float dy = yv - mr[23 + 2*k];
                baseLoss += 0.5f * (dx*dx + dy*dy);
            }
            float mx = -1e30f;
            #pragma unroll
            for (int c = 0; c < NCc; ++c)
                mx = fmaxf(mx, baseo[(2*NKc + 1 + c) * NPIX]);
            float se = 0.0f;
            #pragma unroll
            for (int c = 0; c < NCc; ++c)
                se += __expf(baseo[(2*NKc + 1 + c) * NPIX] - mx);
            int lab = (int)mr[2];
            lab = lab < 0 ? 0 : (lab > NCc - 1 ? NCc - 1 : lab);
            baseLoss += __logf(se) + mx - baseo[(2*NKc + 1 + lab) * NPIX];
            float dc = confv - mr[1];
            confLoss = 2.5f * dc * dc;
        } else if (!silent) {
            confLoss = 0.5f * confv * confv;
        }
    }

    // ---- block reduction (all lanes execute; full mask legal) --------------
    float v0 = baseLoss, v1 = confLoss;
    #pragma unroll
    for (int o = 16; o > 0; o >>= 1) {
        v0 += __shfl_down_sync(0xFFFFFFFFu, v0, o);
        v1 += __shfl_down_sync(0xFFFFFFFFu, v1, o);
    }
    if (lane == 0) s_wred[wid] = make_float2(v0, v1);
    __syncthreads();
    if (tid == 0) {
        float rb = 0.0f, rc = 0.0f;
        #pragma unroll
        for (int j = 0; j < TPB/32; ++j) { rb += s_wred[j].x; rc += s_wred[j].y; }
        g_part[blockIdx.x][0] = rb;
        g_part[blockIdx.x][1] = rc;
    }

    // ---- last-block-done final reduction -----------------------------------
    __threadfence();
    if (tid == 0) {
        int old = atomicAdd(&g_cnt, 1);
        s_last = (old == NBLK - 1);
    }
    __syncthreads();
    if (!s_last) return;

    float rb = 0.0f, rc = 0.0f;
    for (int idx = tid; idx < NBLK; idx += TPB) {
        rb += g_part[idx][0];
        rc += g_part[idx][1];
    }
    #pragma unroll
    for (int o = 16; o > 0; o >>= 1) {
        rb += __shfl_down_sync(0xFFFFFFFFu, rb, o);
        rc += __shfl_down_sync(0xFFFFFFFFu, rc, o);
    }
    if (lane == 0) s_wred[wid] = make_float2(rb, rc);
    __syncthreads();
    if (tid == 0) {
        float tb2 = 0.0f, tc2 = 0.0f;
        #pragma unroll
        for (int j = 0; j < TPB/32; ++j) { tb2 += s_wred[j].x; tc2 += s_wred[j].y; }
        int ev = ((const int*)epoch_ptr)[0];
        if (ev > 1000000 || ev < -1000000) ev = (int)__int_as_float(ev);
        float total = tb2;
        if (ev > 15) total += tc2;
        d_out[0] = total;
        g_cnt = 0;   // reset for graph replay
    }
}

extern "C" void kernel_launch(void* const* d_in, const int* in_sizes, int n_in,
                              void* d_out, int out_size) {
    const float* out_t = (const float*)d_in[0];
    const float* tgt   = (const float*)d_in[1];
    const float* anc   = (const float*)d_in[2];
    const void*  epoch = d_in[3];
    k_main<<<NBLK, TPB>>>(out_t, tgt, anc, epoch, (float*)d_out);
}

// round 8
// speedup vs baseline: 1.2228x; 1.2228x over previous
#include <cuda_runtime.h>
#include <math.h>

// Problem constants
#define NBc   16
#define NAc   5
#define NKc   9
#define NCc   13
#define NHc   38
#define NWc   38
#define MAXTc 50
#define NPIX  (NHc*NWc)        // 1444
#define NANCH (NAc*NPIX)       // 7220
#define NTOTc (NBc*NANCH)      // 115520
#define CHPA  (2*NKc+1+NCc)    // 32
#define TROW  21

#define TPB   128
#define CPB   64                           // cells per block (2 threads/cell)
#define BPB   ((NANCH + CPB - 1)/CPB)      // 113 blocks per batch
#define NBLK  (NBc*BPB)                    // 1808 blocks

// meta record: [0]=key, [1]=tconf, [2]=cls, [3]=pad, [4..21]=(gx,gy)*9
//              [22..39]=(vx,vy)*9
#define MSTRIDE 40

#define SCX   (640.0f/38.0f)
#define SCY   (480.0f/38.0f)
#define DENOM9   57.50150489f
#define STHRESH  34.50090293f   // 0.6 * 9 * (e^2 - 1)
// necessary condition for ssum > STHRESH: some corner d2 < 288.12 (gate @290)
#define GATE2    290.0f

__device__ float g_part[NBLK][2];
__device__ int   g_cnt = 0;

__device__ __forceinline__ float sigf(float x) { return 1.0f / (1.0f + __expf(-x)); }

__global__ void __launch_bounds__(TPB, 12)
k_main(const float* __restrict__ out,
       const float* __restrict__ tgt,
       const float* __restrict__ anc,
       const void*  __restrict__ epoch_ptr,
       float* __restrict__ d_out) {
    __shared__ __align__(16) float s_meta[MAXTc*MSTRIDE];
    __shared__ float  s_t[MAXTc*TROW];
    __shared__ int    s_nv;
    __shared__ float2 s_wred[TPB/32];
    __shared__ bool   s_last;

    const int tid   = threadIdx.x;
    const int lane  = tid & 31;
    const int wid   = tid >> 5;
    const int b     = blockIdx.x / BPB;
    const int split = tid & 1;                       // 0: corners 0-4, 1: 4-8
    const int kb    = split * 4;                     // first owned corner
    const int cell  = (blockIdx.x % BPB) * CPB + (tid >> 1);
    const bool ok   = (cell < NANCH);

    // ---- per-cell channel loads, split by corner (no duplication) ----------
    int a = 0, h = 0, w = 0;
    const float* baseo = out;
    float Pxl[5], Pyl[5];
    float confv_here = 0.0f;
    if (ok) {
        a = cell / NPIX;
        int pix = cell % NPIX;
        h = pix / NWc; w = pix % NWc;
        baseo = out + ((size_t)(b * NAc + a) * CHPA) * NPIX + pix;
        #pragma unroll
        for (int j = 0; j < 5; ++j) {
            int k = kb + j;
            float xv = baseo[(2*k)   * NPIX];
            float yv = baseo[(2*k+1) * NPIX];
            if (k == 0 && split == 0) { xv = sigf(xv); yv = sigf(yv); }
            Pxl[j] = (xv + (float)w) * SCX;
            Pyl[j] = (yv + (float)h) * SCY;
        }
        if (split == 1) confv_here = sigf(baseo[(2*NKc) * NPIX]);
    }
    // broadcast conf (odd lane of each pair loaded it); all lanes execute
    const float confv = __shfl_sync(0xFFFFFFFFu, confv_here, lane | 1);

    // ---- targets -> shared (coalesced) --------------------------------------
    for (int i = tid; i < MAXTc*TROW; i += TPB)
        s_t[i] = tgt[(size_t)b * (MAXTc*TROW) + i];
    __syncthreads();

    // ---- validity prefix via ballots (warp 0) -------------------------------
    if (wid == 0) {
        unsigned m0 = __ballot_sync(0xFFFFFFFFu, s_t[lane*TROW + 1] != 0.0f);
        unsigned m1 = __ballot_sync(0xFFFFFFFFu,
                          (lane < MAXTc - 32) && (s_t[(lane+32)*TROW + 1] != 0.0f));
        if (lane == 0) {
            int nv;
            if (~m0) nv = __ffs(~m0) - 1;
            else {
                unsigned inv = (~m1) & ((1u << (MAXTc - 32)) - 1u);
                nv = inv ? 32 + __ffs(inv) - 1 : MAXTc;
            }
            s_nv = nv;
        }
    }
    __syncthreads();
    const int nv = s_nv;

    // ---- per-target meta straight into shared -------------------------------
    if (tid < nv) {
        const int t = tid;
        const float* tb = &s_t[t*TROW];
        float* mr = &s_meta[t*MSTRIDE];

        float gw = tb[19] * (float)NWc;
        float gh = tb[20] * (float)NHc;
        float best = -1.0f; int bn = 0;
        #pragma unroll
        for (int aa = 0; aa < NAc; ++aa) {
            float aw = anc[2*aa], ah = anc[2*aa+1];
            float cw = fminf(gw, aw), ch = fminf(gh, ah);
            float iou = 0.0f;
            if (cw > 0.0f && ch > 0.0f) {
                float ca = cw * ch;
                iou = ca / (gw * gh + aw * ah - ca);
            }
            if (iou > best) { best = iou; bn = aa; }
        }
        int gi0 = (int)floorf(tb[1] * (float)NWc);
        int gj0 = (int)floorf(tb[2] * (float)NHc);
        mr[0] = __int_as_float((bn << 12) | (gj0 << 6) | gi0);
        mr[2] = tb[0];
        mr[3] = 0.0f;

        float gxp[NKc], gyp[NKc];
        #pragma unroll
        for (int k = 0; k < NKc; ++k) {
            float gx = tb[1 + 2*k], gy = tb[2 + 2*k];
            gxp[k] = gx * 640.0f;  gyp[k] = gy * 480.0f;
            mr[4  + 2*k] = gxp[k];
            mr[5  + 2*k] = gyp[k];
            mr[22 + 2*k] = gx * (float)NWc - (float)gi0;
            mr[23 + 2*k] = gy * (float)NHc - (float)gj0;
        }

        // tconf at pidx-shifted cell
        long long p = (long long)b * NANCH - NPIX + (long long)gj0 * NWc + gi0;
        const long long tot = NTOTc;
        p = ((p % tot) + tot) % tot;
        int b2  = (int)(p / NANCH);
        int rem = (int)(p % NANCH);
        int a2  = rem / NPIX;
        int px2 = rem % NPIX;
        int h2 = px2 / NWc, w2 = px2 % NWc;
        const float* bo2 = out + ((size_t)(b2 * NAc + a2) * CHPA) * NPIX + px2;

        float s = 0.0f;
        #pragma unroll
        for (int k = 0; k < NKc; ++k) {
            float xv = bo2[(2*k)   * NPIX];
            float yv = bo2[(2*k+1) * NPIX];
            if (k == 0) { xv = sigf(xv); yv = sigf(yv); }
            float qx = (xv + (float)w2) * SCX;
            float qy = (yv + (float)h2) * SCY;
            float dx = gxp[k] - qx;
            float dy = gyp[k] - qy;
            float d2 = fmaf(dx, dx, dy * dy);
            if (d2 < 6400.0f) s += __expf(2.0f - sqrtf(d2) * 0.025f) - 1.0f;
        }
        mr[1] = s * (1.0f / DENOM9);
    }
    __syncthreads();

    // ---- match scan (targets split between the 2 lanes) ---------------------
    int m = -1;
    if (ok) {
        const int mykey = (a << 12) | (h << 6) | w;
        for (int t = split; t < nv; t += 2)
            if (__float_as_int(s_meta[t*MSTRIDE]) == mykey) m = t;
    }
    m = max(m, __shfl_xor_sync(0xFFFFFFFFu, m, 1));  // all lanes execute

    // ---- silence scan: each lane checks its 5 owned corners -----------------
    // Gate: ssum > STHRESH requires some corner d2 < 288.12, which trips at
    // least one of the two lanes. Gated lane re-evaluates all 9 exactly.
    int silent = 0;
    if (m < 0) {                       // pair-uniform; no shuffles inside
        for (int t = 0; t < nv; ++t) {
            const float* gp = s_meta + t*MSTRIDE + 4;
            float dmin = 1e30f;
            #pragma unroll
            for (int j = 0; j < 5; ++j) {
                int k = kb + j;
                float dx = Pxl[j] - gp[2*k];
                float dy = Pyl[j] - gp[2*k+1];
                float d2 = fmaf(dx, dx, dy * dy);
                dmin = fminf(dmin, d2);
            }
            if (ok && dmin < GATE2) {
                // rare: full exact 9-corner evaluation (reload; L1 hits)
                float ssum = 0.0f;
                #pragma unroll
                for (int k = 0; k < NKc; ++k) {
                    float xv = baseo[(2*k)   * NPIX];
                    float yv = baseo[(2*k+1) * NPIX];
                    if (k == 0) { xv = sigf(xv); yv = sigf(yv); }
                    float qx = (xv + (float)w) * SCX;
                    float qy = (yv + (float)h) * SCY;
                    float dx = qx - gp[2*k];
                    float dy = qy - gp[2*k+1];
                    float d2 = fmaf(dx, dx, dy * dy);
                    if (d2 < 6400.0f)
                        ssum += __expf(2.0f - sqrtf(d2) * 0.025f) - 1.0f;
                }
                if (ssum > STHRESH) silent = 1;
            }
        }
    }
    silent |= __shfl_xor_sync(0xFFFFFFFFu, silent, 1);  // all lanes execute

    // ---- loss terms (even lane of each pair) --------------------------------
    float baseLoss = 0.0f, confLoss = 0.0f;
    if (ok && split == 0) {
        if (m >= 0) {
            const float* mr = &s_meta[m*MSTRIDE];
            #pragma unroll
            for (int k = 0; k < NKc; ++k) {
                float xv = baseo[(2*k)   * NPIX];
                float yv = baseo[(2*k+1) * NPIX];
                if (k == 0) { xv = sigf(xv); yv = sigf(yv); }
                float dx = xv - mr[22 + 2*k];
                float dy = yv - mr[23 + 2*k];
                baseLoss += 0.5f * (dx*dx + dy*dy);
            }
            float mx = -1e30f;
            #pragma unroll
            for (int c = 0; c < NCc; ++c)
                mx = fmaxf(mx, baseo[(2*NKc + 1 + c) * NPIX]);
            float se = 0.0f;
            #pragma unroll
            for (int c = 0; c < NCc; ++c)
                se += __expf(baseo[(2*NKc + 1 + c) * NPIX] - mx);
            int lab = (int)mr[2];
            lab = lab < 0 ? 0 : (lab > NCc - 1 ? NCc - 1 : lab);
            baseLoss += __logf(se) + mx - baseo[(2*NKc + 1 + lab) * NPIX];
            float dc = confv - mr[1];
            confLoss = 2.5f * dc * dc;
        } else if (!silent) {
            confLoss = 0.5f * confv * confv;
        }
    }

    // ---- block reduction ----------------------------------------------------
    float v0 = baseLoss, v1 = confLoss;
    #pragma unroll
    for (int o = 16; o > 0; o >>= 1) {
        v0 += __shfl_down_sync(0xFFFFFFFFu, v0, o);
        v1 += __shfl_down_sync(0xFFFFFFFFu, v1, o);
    }
    if (lane == 0) s_wred[wid] = make_float2(v0, v1);
    __syncthreads();
    if (tid == 0) {
        float rb = 0.0f, rc = 0.0f;
        #pragma unroll
        for (int j = 0; j < TPB/32; ++j) { rb += s_wred[j].x; rc += s_wred[j].y; }
        g_part[blockIdx.x][0] = rb;
        g_part[blockIdx.x][1] = rc;
    }

    // ---- last-block-done final reduction ------------------------------------
    __threadfence();
    if (tid == 0) {
        int old = atomicAdd(&g_cnt, 1);
        s_last = (old == NBLK - 1);
    }
    __syncthreads();
    if (!s_last) return;

    float rb = 0.0f, rc = 0.0f;
    for (int idx = tid; idx < NBLK; idx += TPB) {
        rb += g_part[idx][0];
        rc += g_part[idx][1];
    }
    #pragma unroll
    for (int o = 16; o > 0; o >>= 1) {
        rb += __shfl_down_sync(0xFFFFFFFFu, rb, o);
        rc += __shfl_down_sync(0xFFFFFFFFu, rc, o);
    }
    if (lane == 0) s_wred[wid] = make_float2(rb, rc);
    __syncthreads();
    if (tid == 0) {
        float tb2 = 0.0f, tc2 = 0.0f;
        #pragma unroll
        for (int j = 0; j < TPB/32; ++j) { tb2 += s_wred[j].x; tc2 += s_wred[j].y; }
        int ev = ((const int*)epoch_ptr)[0];
        if (ev > 1000000 || ev < -1000000) ev = (int)__int_as_float(ev);
        float total = tb2;
        if (ev > 15) total += tc2;
        d_out[0] = total;
        g_cnt = 0;   // reset for graph replay
    }
}

extern "C" void kernel_launch(void* const* d_in, const int* in_sizes, int n_in,
                              void* d_out, int out_size) {
    const float* out_t = (const float*)d_in[0];
    const float* tgt   = (const float*)d_in[1];
    const float* anc   = (const float*)d_in[2];
    const void*  epoch = d_in[3];
    k_main<<<NBLK, TPB>>>(out_t, tgt, anc, epoch, (float*)d_out);
}

// round 9
// speedup vs baseline: 2.0067x; 1.6411x over previous
#include <cuda_runtime.h>
#include <math.h>

// Problem constants
#define NBc   16
#define NAc   5
#define NKc   9
#define NCc   13
#define NHc   38
#define NWc   38
#define MAXTc 50
#define NPIX  (NHc*NWc)        // 1444
#define NANCH (NAc*NPIX)       // 7220
#define NTOTc (NBc*NANCH)      // 115520
#define CHPA  (2*NKc+1+NCc)    // 32
#define TROW  21

#define TPB   128
#define BPB   ((NANCH + TPB - 1)/TPB)  // 57 blocks per batch
#define NBLK  (NBc*BPB)                // 912

#define NTFAST 8                        // unrolled target count (nv <= 8 here)

// meta record: [0]=key, [1]=tconf, [2]=cls, [3]=pad, [4..21]=(gx,gy)*9,
//              [22..39]=(vx,vy)*9
#define MSTRIDE 40

#define SCX   (640.0f/38.0f)
#define SCY   (480.0f/38.0f)
#define DENOM9   57.50150489f
#define STHRESH  34.50090293f   // 0.6 * 9 * (e^2 - 1)
// ssum > STHRESH needs max term >= STHRESH/9 -> some corner d2 < 288.12
#define GATE2    290.0f

__device__ float g_part[NBLK][2];
__device__ int   g_cnt = 0;

__device__ __forceinline__ float sigf(float x) { return 1.0f / (1.0f + __expf(-x)); }

__global__ void __launch_bounds__(TPB, 6)
k_main(const float* __restrict__ out,
       const float* __restrict__ tgt,
       const float* __restrict__ anc,
       const void*  __restrict__ epoch_ptr,
       float* __restrict__ d_out) {
    __shared__ __align__(16) float s_meta[MAXTc*MSTRIDE];
    __shared__ float  s_t[MAXTc*TROW];
    __shared__ int    s_nv;
    __shared__ float2 s_wred[TPB/32];
    __shared__ bool   s_last;

    const int tid  = threadIdx.x;
    const int lane = tid & 31;
    const int wid  = tid >> 5;
    const int b    = blockIdx.x / BPB;
    const int cell = (blockIdx.x % BPB) * TPB + tid;
    const bool ok  = (cell < NANCH);

    // ---- per-cell channel loads, issued early ------------------------------
    int a = 0, h = 0, w = 0;
    const float* baseo = out;
    float Px[NKc], Py[NKc], confv = 0.0f;
    if (ok) {
        a = cell / NPIX;
        int pix = cell % NPIX;
        h = pix / NWc; w = pix % NWc;
        baseo = out + ((size_t)(b * NAc + a) * CHPA) * NPIX + pix;
        float rc = baseo[(2*NKc) * NPIX];
        #pragma unroll
        for (int k = 0; k < NKc; ++k) {
            float xv = baseo[(2*k)   * NPIX];
            float yv = baseo[(2*k+1) * NPIX];
            if (k == 0) { xv = sigf(xv); yv = sigf(yv); }
            Px[k] = (xv + (float)w) * SCX;
            Py[k] = (yv + (float)h) * SCY;
        }
        confv = sigf(rc);
    }

    // ---- targets -> shared (coalesced) -------------------------------------
    for (int i = tid; i < MAXTc*TROW; i += TPB)
        s_t[i] = tgt[(size_t)b * (MAXTc*TROW) + i];
    __syncthreads();

    // ---- validity prefix via ballots (warp 0) ------------------------------
    if (wid == 0) {
        unsigned m0 = __ballot_sync(0xFFFFFFFFu, s_t[lane*TROW + 1] != 0.0f);
        unsigned m1 = __ballot_sync(0xFFFFFFFFu,
                          (lane < MAXTc - 32) && (s_t[(lane+32)*TROW + 1] != 0.0f));
        if (lane == 0) {
            int nv;
            if (~m0) nv = __ffs(~m0) - 1;
            else {
                unsigned inv = (~m1) & ((1u << (MAXTc - 32)) - 1u);
                nv = inv ? 32 + __ffs(inv) - 1 : MAXTc;
            }
            s_nv = nv;
        }
    }
    __syncthreads();
    const int nv = s_nv;

    // ---- per-target meta -> shared; sentinel-pad slots [nv, 8) -------------
    if (tid < nv) {
        const int t = tid;
        const float* tb = &s_t[t*TROW];
        float* mr = &s_meta[t*MSTRIDE];

        float gw = tb[19] * (float)NWc;
        float gh = tb[20] * (float)NHc;
        float best = -1.0f; int bn = 0;
        #pragma unroll
        for (int aa = 0; aa < NAc; ++aa) {
            float aw = anc[2*aa], ah = anc[2*aa+1];
            float cw = fminf(gw, aw), ch = fminf(gh, ah);
            float iou = 0.0f;
            if (cw > 0.0f && ch > 0.0f) {
                float ca = cw * ch;
                iou = ca / (gw * gh + aw * ah - ca);
            }
            if (iou > best) { best = iou; bn = aa; }
        }
        int gi0 = (int)floorf(tb[1] * (float)NWc);
        int gj0 = (int)floorf(tb[2] * (float)NHc);
        mr[0] = __int_as_float((bn << 12) | (gj0 << 6) | gi0);
        mr[2] = tb[0];
        mr[3] = 0.0f;

        float gxp[NKc], gyp[NKc];
        #pragma unroll
        for (int k = 0; k < NKc; ++k) {
            float gx = tb[1 + 2*k], gy = tb[2 + 2*k];
            gxp[k] = gx * 640.0f;  gyp[k] = gy * 480.0f;
            mr[4  + 2*k] = gxp[k];
            mr[5  + 2*k] = gyp[k];
            mr[22 + 2*k] = gx * (float)NWc - (float)gi0;
            mr[23 + 2*k] = gy * (float)NHc - (float)gj0;
        }

        // tconf at pidx-shifted cell
        long long p = (long long)b * NANCH - NPIX + (long long)gj0 * NWc + gi0;
        const long long tot = NTOTc;
        p = ((p % tot) + tot) % tot;
        int b2  = (int)(p / NANCH);
        int rem = (int)(p % NANCH);
        int a2  = rem / NPIX;
        int px2 = rem % NPIX;
        int h2 = px2 / NWc, w2 = px2 % NWc;
        const float* bo2 = out + ((size_t)(b2 * NAc + a2) * CHPA) * NPIX + px2;

        float s = 0.0f;
        #pragma unroll
        for (int k = 0; k < NKc; ++k) {
            float xv = bo2[(2*k)   * NPIX];
            float yv = bo2[(2*k+1) * NPIX];
            if (k == 0) { xv = sigf(xv); yv = sigf(yv); }
            float qx = (xv + (float)w2) * SCX;
            float qy = (yv + (float)h2) * SCY;
            float dx = gxp[k] - qx;
            float dy = gyp[k] - qy;
            float d2 = fmaf(dx, dx, dy * dy);
            if (d2 < 6400.0f) s += __expf(2.0f - sqrtf(d2) * 0.025f) - 1.0f;
        }
        mr[1] = s * (1.0f / DENOM9);
    } else if (tid < NTFAST) {
        // sentinel target: never matches, never gates
        float* mr = &s_meta[tid*MSTRIDE];
        mr[0] = __int_as_float(0x7FFFFFFF);
        #pragma unroll
        for (int k = 0; k < NKc; ++k) {
            mr[4 + 2*k] = 1.0e9f;
            mr[5 + 2*k] = 1.0e9f;
        }
    }
    __syncthreads();

    // ---- fused match + gate scan: fully unrolled, branch-free --------------
    float baseLoss = 0.0f, confLoss = 0.0f;

    if (ok) {
        const int mykey = (a << 12) | (h << 6) | w;
        int m = -1;
        unsigned gatemask = 0;
        int silent = 0;

        #pragma unroll
        for (int t = 0; t < NTFAST; ++t) {
            const float* mr = s_meta + t*MSTRIDE;
            if (__float_as_int(mr[0]) == mykey) m = t;      // predicated SEL
            const float2* gp = (const float2*)(mr + 4);
            float dmin = 1e30f;
            #pragma unroll
            for (int k = 0; k < NKc; ++k) {
                float2 g = gp[k];
                float dx = Px[k] - g.x;
                float dy = Py[k] - g.y;
                float d2 = fmaf(dx, dx, dy * dy);
                dmin = fminf(dmin, d2);
            }
            gatemask |= (dmin < GATE2) ? (1u << t) : 0u;    // predicated
        }
        // dynamic tail (nv > 8 — not hit for this data, kept for correctness)
        for (int t = NTFAST; t < nv; ++t) {
            const float* mr = s_meta + t*MSTRIDE;
            if (__float_as_int(mr[0]) == mykey) m = t;
            const float2* gp = (const float2*)(mr + 4);
            float dmin = 1e30f;
            #pragma unroll
            for (int k = 0; k < NKc; ++k) {
                float2 g = gp[k];
                float dx = Px[k] - g.x;
                float dy = Py[k] - g.y;
                dmin = fminf(dmin, fmaf(dx, dx, dy * dy));
            }
            if (dmin < GATE2) {
                float ssum = 0.0f;
                #pragma unroll
                for (int k = 0; k < NKc; ++k) {
                    float dx = Px[k] - gp[k].x;
                    float dy = Py[k] - gp[k].y;
                    float d2 = fmaf(dx, dx, dy * dy);
                    if (d2 < 6400.0f)
                        ssum += __expf(2.0f - sqrtf(d2) * 0.025f) - 1.0f;
                }
                if (ssum > STHRESH) silent = 1;
            }
        }

        if (m >= 0) {
            // matched cell: coord + CE + obj-conf loss (rare path)
            const float* mr = &s_meta[m*MSTRIDE];
            #pragma unroll
            for (int k = 0; k < NKc; ++k) {
                float xv = baseo[(2*k)   * NPIX];
                float yv = baseo[(2*k+1) * NPIX];
                if (k == 0) { xv = sigf(xv); yv = sigf(yv); }
                float dx = xv - mr[22 + 2*k];
                float dy = yv - mr[23 + 2*k];
                baseLoss += 0.5f * (dx*dx + dy*dy);
            }
            float mx = -1e30f;
            #pragma unroll
            for (int c = 0; c < NCc; ++c)
                mx = fmaxf(mx, baseo[(2*NKc + 1 + c) * NPIX]);
            float se = 0.0f;
            #pragma unroll
            for (int c = 0; c < NCc; ++c)
                se += __expf(baseo[(2*NKc + 1 + c) * NPIX] - mx);
            int lab = (int)mr[2];
            lab = lab < 0 ? 0 : (lab > NCc - 1 ? NCc - 1 : lab);
            baseLoss += __logf(se) + mx - baseo[(2*NKc + 1 + lab) * NPIX];
            float dc = confv - mr[1];
            confLoss = 2.5f * dc * dc;
        } else {
            // deferred exact evaluation of gated targets (rare)
            while (gatemask && !silent) {
                int t = __ffs(gatemask) - 1;
                gatemask &= gatemask - 1;
                const float2* gp = (const float2*)(s_meta + t*MSTRIDE + 4);
                float ssum = 0.0f;
                #pragma unroll
                for (int k = 0; k < NKc; ++k) {
                    float dx = Px[k] - gp[k].x;
                    float dy = Py[k] - gp[k].y;
                    float d2 = fmaf(dx, dx, dy * dy);
                    if (d2 < 6400.0f)
                        ssum += __expf(2.0f - sqrtf(d2) * 0.025f) - 1.0f;
                }
                if (ssum > STHRESH) silent = 1;
            }
            if (!silent) confLoss = 0.5f * confv * confv;
        }
    }

    // ---- block reduction ----------------------------------------------------
    float v0 = baseLoss, v1 = confLoss;
    #pragma unroll
    for (int o = 16; o > 0; o >>= 1) {
        v0 += __shfl_down_sync(0xFFFFFFFFu, v0, o);
        v1 += __shfl_down_sync(0xFFFFFFFFu, v1, o);
    }
    if (lane == 0) s_wred[wid] = make_float2(v0, v1);
    __syncthreads();
    if (tid == 0) {
        float rb = 0.0f, rc = 0.0f;
        #pragma unroll
        for (int j = 0; j < TPB/32; ++j) { rb += s_wred[j].x; rc += s_wred[j].y; }
        g_part[blockIdx.x][0] = rb;
        g_part[blockIdx.x][1] = rc;
    }

    // ---- last-block-done final reduction ------------------------------------
    __threadfence();
    if (tid == 0) {
        int old = atomicAdd(&g_cnt, 1);
        s_last = (old == NBLK - 1);
    }
    __syncthreads();
    if (!s_last) return;

    float rb = 0.0f, rc = 0.0f;
    for (int idx = tid; idx < NBLK; idx += TPB) {
        rb += g_part[idx][0];
        rc += g_part[idx][1];
    }
    #pragma unroll
    for (int o = 16; o > 0; o >>= 1) {
        rb += __shfl_down_sync(0xFFFFFFFFu, rb, o);
        rc += __shfl_down_sync(0xFFFFFFFFu, rc, o);
    }
    if (lane == 0) s_wred[wid] = make_float2(rb, rc);
    __syncthreads();
    if (tid == 0) {
        float tb2 = 0.0f, tc2 = 0.0f;
        #pragma unroll
        for (int j = 0; j < TPB/32; ++j) { tb2 += s_wred[j].x; tc2 += s_wred[j].y; }
        int ev = ((const int*)epoch_ptr)[0];
        if (ev > 1000000 || ev < -1000000) ev = (int)__int_as_float(ev);
        float total = tb2;
        if (ev > 15) total += tc2;
        d_out[0] = total;
        g_cnt = 0;   // reset for graph replay
    }
}

extern "C" void kernel_launch(void* const* d_in, const int* in_sizes, int n_in,
                              void* d_out, int out_size) {
    const float* out_t = (const float*)d_in[0];
    const float* tgt   = (const float*)d_in[1];
    const float* anc   = (const float*)d_in[2];
    const void*  epoch = d_in[3];
    k_main<<<NBLK, TPB>>>(out_t, tgt, anc, epoch, (float*)d_out);
}